// round 14
// baseline (speedup 1.0000x reference)
#include <cuda_runtime.h>
#include <cuda_bf16.h>
#include <math.h>
#include <stdint.h>

#define NN 100000
#define NE 1600000
#define F  128
#define SCAN_B 1024
#define NBLK_SCAN 98   // ceil(100000/1024)
#define NS_ROWS 400
#define NS_BLOCKS ((NN + NS_ROWS - 1) / NS_ROWS)
#define NBLK_GEMM ((NN + 127) / 128)   // 782
#define NPAD (NBLK_GEMM * 128)          // 100096 padded rows

// ---------------- device scratch (no allocations allowed) ----------------
struct GraphScratch {          // zeroed by memset
    int   deg[NN];
    float cw[NN];
};
struct AccumScratch {          // zeroed by memset
    float colsumA[F], colsqA[F];   // layer-0 stats
    float colsumB[F], colsqB[F];   // layer-1 stats
    float msum[F], wa[F];
    int   ticket;                  // nsfinal last-block ticket
    int   sync2;                   // scanfill grid-sync counter
    int   flag[NBLK_SCAN];
    int   bsum[NBLK_SCAN];
};
static __device__ GraphScratch g_gs;
static __device__ AccumScratch g_acc;

static __device__ int   g_rowstart[NN];
static __device__ int   g_cursor[NN];
static __device__ int   g_col[NE];
static __device__ float g_invdeg[NN];

static __device__ __align__(256) __nv_bfloat16 g_X0[NN * F];      // features bf16
static __device__ __align__(256) __nv_bfloat16 g_CAT[NPAD * 256]; // [Xbn | AGG] (pad rows stay 0)
static __device__ __align__(256) __nv_bfloat16 g_H1[NPAD * F];    // layer outs (pre-BN)
static __device__ __align__(256) __nv_bfloat16 g_H2[NPAD * F];
static __device__ __align__(256) __nv_bfloat16 g_WT[2][128][256]; // W n-major bf16

// ---------------- helpers ----------------

__device__ __forceinline__ void mma_bf16(float c[4], const uint32_t a[4], const uint32_t b[2]) {
    asm volatile(
        "mma.sync.aligned.m16n8k16.row.col.f32.bf16.bf16.f32 "
        "{%0,%1,%2,%3}, {%4,%5,%6,%7}, {%8,%9}, {%0,%1,%2,%3};"
        : "+f"(c[0]), "+f"(c[1]), "+f"(c[2]), "+f"(c[3])
        : "r"(a[0]), "r"(a[1]), "r"(a[2]), "r"(a[3]), "r"(b[0]), "r"(b[1]));
}

__device__ __forceinline__ float2 bf2f2(uint32_t p) {
    return __bfloat1622float2(*(const __nv_bfloat162*)&p);
}
__device__ __forceinline__ uint32_t f22bf(float2 f) {
    __nv_bfloat162 h = __float22bfloat162_rn(f);
    return *(const uint32_t*)&h;
}
__device__ __forceinline__ uint32_t smem_u32(const void* p) {
    uint32_t a;
    asm("{ .reg .u64 t; cvta.to.shared.u64 t, %1; cvt.u32.u64 %0, t; }" : "=r"(a) : "l"(p));
    return a;
}
__device__ __forceinline__ void cp_async16(uint32_t dst, const void* src) {
    asm volatile("cp.async.cg.shared.global [%0], [%1], 16;" :: "r"(dst), "l"(src));
}
// packed f32x2: pack two u32 (f32 bit patterns) into a 64-bit operand
__device__ __forceinline__ uint64_t pack2(uint32_t lo, uint32_t hi) {
    uint64_t p;
    asm("mov.b64 %0, {%1,%2};" : "=l"(p) : "r"(lo), "r"(hi));
    return p;
}
__device__ __forceinline__ uint64_t addf2(uint64_t a, uint64_t b) {
    uint64_t r;
    asm("add.rn.f32x2 %0, %1, %2;" : "=l"(r) : "l"(a), "l"(b));
    return r;
}
// bf16x2 word -> packed f32x2 (exact: bf16 is the top half of f32)
__device__ __forceinline__ uint64_t bfw2f2(uint32_t w) {
    return pack2(w << 16, w & 0xffff0000u);
}

// Recompute BN affine coefficients into smem (first 128 threads), then sync.
__device__ __forceinline__ void bn_coeffs(const float* __restrict__ colsum,
                                          const float* __restrict__ colsq,
                                          const float* __restrict__ gam,
                                          const float* __restrict__ bet,
                                          float* s_sc, float* s_sh, int tid) {
    if (tid < F) {
        float inv_n = 1.0f / (float)NN;
        float mu  = colsum[tid] * inv_n;
        float var = colsq[tid] * inv_n - mu * mu;
        float sc  = gam[tid] * rsqrtf(var + 1e-5f);
        s_sc[tid] = sc;
        s_sh[tid] = bet[tid] - mu * sc;
    }
    __syncthreads();
}

// ---------------- prep: histogram + feature bf16 + CAT self half + weight transpose ----------------
__global__ void k_prep(const float* __restrict__ feat, const int* __restrict__ dst,
                       const float* __restrict__ Ws0, const float* __restrict__ Wn0,
                       const float* __restrict__ Ws1, const float* __restrict__ Wn1) {
    int gid = blockIdx.x * blockDim.x + threadIdx.x;
    float4 v = ((const float4*)feat)[gid];
    uint2 o;
    o.x = f22bf(make_float2(v.x, v.y));
    o.y = f22bf(make_float2(v.z, v.w));
    *(uint2*)&g_X0[(size_t)gid * 4] = o;
    // layer-0 CAT self half (cols 0..127)
    {
        int node = gid >> 5;
        int c4   = (gid & 31) * 4;
        *(uint2*)&g_CAT[(size_t)node * 256 + c4] = o;
    }
    if (gid < NE / 4) {
        int4 d4 = ((const int4*)dst)[gid];
        atomicAdd(&g_gs.deg[d4.x], 1);
        atomicAdd(&g_gs.deg[d4.y], 1);
        atomicAdd(&g_gs.deg[d4.z], 1);
        atomicAdd(&g_gs.deg[d4.w], 1);
    }
    if (gid < 2 * 256 * 128) {
        int L = gid >> 15;
        int r = gid & 32767;
        int k = r >> 7, n = r & 127;
        const float* W = (L == 0) ? ((k < 128) ? Ws0 : Wn0)
                                  : ((k < 128) ? Ws1 : Wn1);
        g_WT[L][n][k] = __float2bfloat16(W[(k & 127) * 128 + n]);
    }
}

// ---------------- scan + bucket fill (merged; 98 co-resident blocks) ----------------
__global__ void k_scanfill(const int* __restrict__ src, const int* __restrict__ dst) {
    __shared__ int s[SCAN_B];
    __shared__ int s_prefix;
    int t = threadIdx.x;
    int b = blockIdx.x;
    int i = b * SCAN_B + t;
    int v = (i < NN) ? g_gs.deg[i] : 0;
    s[t] = v;
    __syncthreads();
    for (int off = 1; off < SCAN_B; off <<= 1) {
        int x = (t >= off) ? s[t - off] : 0;
        __syncthreads();
        s[t] += x;
        __syncthreads();
    }
    int incl = s[t];
    if (t == SCAN_B - 1) {
        g_acc.bsum[b] = incl;
        __threadfence();
        ((volatile int*)g_acc.flag)[b] = 1;
    }
    if (t < 32) {
        int sum = 0;
        for (int bb = t; bb < b; bb += 32) {
            while (((volatile int*)g_acc.flag)[bb] == 0) {}
            __threadfence();
            sum += ((volatile int*)g_acc.bsum)[bb];
        }
        #pragma unroll
        for (int off = 16; off > 0; off >>= 1)
            sum += __shfl_xor_sync(0xffffffffu, sum, off);
        if (t == 0) s_prefix = sum;
    }
    __syncthreads();
    if (i < NN) {
        int d = v;
        int start = s_prefix + incl - d;
        g_rowstart[i] = start;
        g_cursor[i]   = start;
        g_invdeg[i]   = 1.0f / (float)max(d, 1);
    }
    __threadfence();
    __syncthreads();
    if (t == 0) {
        atomicAdd(&g_acc.sync2, 1);
        while (((volatile int*)&g_acc.sync2)[0] < NBLK_SCAN) {}
    }
    __syncthreads();
    __threadfence();
    int gid = b * SCAN_B + t;
    const int4* s4p = (const int4*)src;
    const int4* d4p = (const int4*)dst;
    for (int q = gid; q < NE / 4; q += NBLK_SCAN * SCAN_B) {
        int4 s4 = s4p[q];
        int4 d4 = d4p[q];
        #define ONEEDGE(ss, dd) {                      \
            int pos = atomicAdd(&g_cursor[dd], 1);      \
            g_col[pos] = ss;                            \
            atomicAdd(&g_gs.cw[ss], g_invdeg[dd]); }
        ONEEDGE(s4.x, d4.x);
        ONEEDGE(s4.y, d4.y);
        ONEEDGE(s4.z, d4.z);
        ONEEDGE(s4.w, d4.w);
        #undef ONEEDGE
    }
}

// ---------------- aggregation: warp-per-node; writes CAT = [own | agg] ----------------
// BN=false: self half already written by k_prep; packed f32x2 accumulation.
template<bool BN>
__global__ void k_agg(const __nv_bfloat16* __restrict__ Hin,
                      const float* __restrict__ colsum, const float* __restrict__ colsq,
                      const float* __restrict__ gam, const float* __restrict__ bet) {
    __shared__ float s_sc[F], s_sh[F];
    int tid = threadIdx.x;
    if (BN) bn_coeffs(colsum, colsq, gam, bet, s_sc, s_sh, tid);

    int warp = (blockIdx.x * blockDim.x + tid) >> 5;
    int lane = tid & 31;
    if (warp >= NN) return;
    int c0 = lane * 4;
    int start = g_rowstart[warp];
    int d     = g_gs.deg[warp];
    float w = g_invdeg[warp];

    if (!BN) {
        // packed f32x2 accumulation (bit-identical to scalar tree)
        uint64_t acc01 = 0ull, acc23 = 0ull;
        int j = 0;
        for (; j + 4 <= d; j += 4) {
            int s0 = g_col[start + j];
            int s1 = g_col[start + j + 1];
            int s2 = g_col[start + j + 2];
            int s3 = g_col[start + j + 3];
            uint2 rA = *(const uint2*)(Hin + (size_t)s0 * F + c0);
            uint2 rB = *(const uint2*)(Hin + (size_t)s1 * F + c0);
            uint2 rC = *(const uint2*)(Hin + (size_t)s2 * F + c0);
            uint2 rD = *(const uint2*)(Hin + (size_t)s3 * F + c0);
            uint64_t ab01 = addf2(bfw2f2(rA.x), bfw2f2(rB.x));
            uint64_t cd01 = addf2(bfw2f2(rC.x), bfw2f2(rD.x));
            uint64_t ab23 = addf2(bfw2f2(rA.y), bfw2f2(rB.y));
            uint64_t cd23 = addf2(bfw2f2(rC.y), bfw2f2(rD.y));
            acc01 = addf2(acc01, addf2(ab01, cd01));
            acc23 = addf2(acc23, addf2(ab23, cd23));
        }
        for (; j < d; j++) {
            int s = g_col[start + j];
            uint2 r = *(const uint2*)(Hin + (size_t)s * F + c0);
            acc01 = addf2(acc01, bfw2f2(r.x));
            acc23 = addf2(acc23, bfw2f2(r.y));
        }
        uint32_t a0, a1, a2, a3;
        asm("mov.b64 {%0,%1}, %2;" : "=r"(a0), "=r"(a1) : "l"(acc01));
        asm("mov.b64 {%0,%1}, %2;" : "=r"(a2), "=r"(a3) : "l"(acc23));
        uint2 o;
        o.x = f22bf(make_float2(__uint_as_float(a0) * w, __uint_as_float(a1) * w));
        o.y = f22bf(make_float2(__uint_as_float(a2) * w, __uint_as_float(a3) * w));
        *(uint2*)(g_CAT + (size_t)warp * 256 + 128 + c0) = o;
    } else {
        float4 sc = *(const float4*)&s_sc[c0];
        float4 sh = *(const float4*)&s_sh[c0];
        float4 acc = make_float4(0.f, 0.f, 0.f, 0.f);

        #define LOADROW(sidx, r01, r23) {                                   \
            uint2 raw = *(const uint2*)(Hin + (size_t)(sidx) * F + c0);     \
            r01 = bf2f2(raw.x); r23 = bf2f2(raw.y);                         \
            r01.x = fmaxf(r01.x * sc.x + sh.x, 0.f);                         \
            r01.y = fmaxf(r01.y * sc.y + sh.y, 0.f);                         \
            r23.x = fmaxf(r23.x * sc.z + sh.z, 0.f);                         \
            r23.y = fmaxf(r23.y * sc.w + sh.w, 0.f); }

        int j = 0;
        for (; j + 4 <= d; j += 4) {
            int s0 = g_col[start + j];
            int s1 = g_col[start + j + 1];
            int s2 = g_col[start + j + 2];
            int s3 = g_col[start + j + 3];
            float2 a01, a23, b01, b23, c01, c23, d01, d23;
            LOADROW(s0, a01, a23);
            LOADROW(s1, b01, b23);
            LOADROW(s2, c01, c23);
            LOADROW(s3, d01, d23);
            acc.x += (a01.x + b01.x) + (c01.x + d01.x);
            acc.y += (a01.y + b01.y) + (c01.y + d01.y);
            acc.z += (a23.x + b23.x) + (c23.x + d23.x);
            acc.w += (a23.y + b23.y) + (c23.y + d23.y);
        }
        for (; j < d; j++) {
            int s = g_col[start + j];
            float2 a01, a23;
            LOADROW(s, a01, a23);
            acc.x += a01.x; acc.y += a01.y; acc.z += a23.x; acc.w += a23.y;
        }
        // own row (BN-applied) -> CAT[:,0:128]
        {
            float2 o01, o23;
            LOADROW(warp, o01, o23);
            uint2 ow;
            ow.x = f22bf(o01);
            ow.y = f22bf(o23);
            *(uint2*)(g_CAT + (size_t)warp * 256 + c0) = ow;
        }
        #undef LOADROW
        uint2 o;
        o.x = f22bf(make_float2(acc.x * w, acc.y * w));
        o.y = f22bf(make_float2(acc.z * w, acc.w * w));
        *(uint2*)(g_CAT + (size_t)warp * 256 + 128 + c0) = o;
    }
}

// ---------------- bf16 tensor-core GEMM, N-split 64, cp.async 2-stage x 64-k ----------------
// Block (bx, by): rows bx*128..+127, cols by*64..+63.
// Hout[NPAD][128] = relu(CAT[NPAD][256] @ WT^T + b).

#define LDH 72                              // bf16 per row (64 data + 8 pad); 36 words
#define STAGE_A (128 * LDH * 2)             // 18432 B
#define STAGE_B (64 * LDH * 2)              // 9216 B

__global__ __launch_bounds__(256, 3) void k_gemm(
    const __nv_bfloat16* __restrict__ CAT,
    const __nv_bfloat16* __restrict__ WT,
    const float* __restrict__ bias,
    __nv_bfloat16* __restrict__ Hout)
{
    __shared__ __align__(16) __nv_bfloat16 As[2][128 * LDH];
    __shared__ __align__(16) __nv_bfloat16 Bs[2][64 * LDH];

    int tid  = threadIdx.x;
    int lane = tid & 31;
    int wid  = tid >> 5;
    int warp_m = wid >> 1;         // 0..3  (32-row slice)
    int warp_n = wid & 1;          // 0..1  (32-col slice of 64)
    int g  = lane >> 2;            // 0..7
    int tg = lane & 3;             // 0..3
    int row0 = blockIdx.x * 128;
    int ncol0 = blockIdx.y * 64;
    const __nv_bfloat16* WTh = WT + (size_t)ncol0 * 256;

    uint32_t sA = smem_u32(As);
    uint32_t sB = smem_u32(Bs);

    #define LOAD_STAGE(kc64, buf) {                                                 \
        _Pragma("unroll")                                                            \
        for (int p = 0; p < 4; p++) {                                                \
            int id = p * 256 + tid;          /* 1024 A chunks */                     \
            int r = id >> 3, q = id & 7;                                             \
            cp_async16(sA + (buf) * STAGE_A + (r * LDH + q * 8) * 2,                 \
                       CAT + (size_t)(row0 + r) * 256 + (kc64) * 64 + q * 8);        \
        }                                                                            \
        _Pragma("unroll")                                                            \
        for (int p = 0; p < 2; p++) {                                                \
            int id = p * 256 + tid;          /* 512 B chunks */                      \
            int r = id >> 3, q = id & 7;                                             \
            cp_async16(sB + (buf) * STAGE_B + (r * LDH + q * 8) * 2,                 \
                       WTh + (size_t)r * 256 + (kc64) * 64 + q * 8);                 \
        }                                                                            \
        asm volatile("cp.async.commit_group;" ::: "memory"); }

    float c[2][4][4];
    #pragma unroll
    for (int mt = 0; mt < 2; mt++)
        #pragma unroll
        for (int nt = 0; nt < 4; nt++)
            #pragma unroll
            for (int r = 0; r < 4; r++) c[mt][nt][r] = 0.f;

    LOAD_STAGE(0, 0);
    LOAD_STAGE(1, 1);

    for (int i = 0; i < 4; i++) {
        int buf = i & 1;
        if (i < 3) asm volatile("cp.async.wait_group 1;" ::: "memory");
        else       asm volatile("cp.async.wait_group 0;" ::: "memory");
        __syncthreads();

        const uint32_t* Asu = (const uint32_t*)As[buf];
        const uint32_t* Bsu = (const uint32_t*)Bs[buf];
        #pragma unroll
        for (int ks = 0; ks < 4; ks++) {
            int k0h = ks * 8;                 // word offset within 36-word row
            uint32_t a[2][4];
            #pragma unroll
            for (int mt = 0; mt < 2; mt++) {
                int bm = warp_m * 32 + mt * 16;
                int base = (bm + g) * (LDH / 2) + k0h + tg;
                a[mt][0] = Asu[base];
                a[mt][1] = Asu[base + 8 * (LDH / 2)];
                a[mt][2] = Asu[base + 4];
                a[mt][3] = Asu[base + 8 * (LDH / 2) + 4];
            }
            uint32_t b[4][2];
            #pragma unroll
            for (int nt = 0; nt < 4; nt++) {
                int bn = warp_n * 32 + nt * 8 + g;
                int base = bn * (LDH / 2) + k0h + tg;
                b[nt][0] = Bsu[base];
                b[nt][1] = Bsu[base + 4];
            }
            #pragma unroll
            for (int mt = 0; mt < 2; mt++)
                #pragma unroll
                for (int nt = 0; nt < 4; nt++)
                    mma_bf16(c[mt][nt], a[mt], b[nt]);
        }
        __syncthreads();
        if (i < 2) LOAD_STAGE(i + 2, buf);
    }
    #undef LOAD_STAGE

    // ---- epilogue: bias + relu + bf16 store ----
    #pragma unroll
    for (int mt = 0; mt < 2; mt++) {
        int rA = row0 + warp_m * 32 + mt * 16 + g;
        int rB = rA + 8;
        #pragma unroll
        for (int nt = 0; nt < 4; nt++) {
            int col = ncol0 + warp_n * 32 + nt * 8 + tg * 2;
            float2 bb = *(const float2*)&bias[col];
            float v0 = fmaxf(c[mt][nt][0] + bb.x, 0.f);
            float v1 = fmaxf(c[mt][nt][1] + bb.y, 0.f);
            float v2 = fmaxf(c[mt][nt][2] + bb.x, 0.f);
            float v3 = fmaxf(c[mt][nt][3] + bb.y, 0.f);
            *(uint32_t*)&Hout[(size_t)rA * F + col] = f22bf(make_float2(v0, v1));
            *(uint32_t*)&Hout[(size_t)rB * F + col] = f22bf(make_float2(v2, v3));
        }
    }
}

// ---------------- column stats: colsum/colsq over valid rows of H ----------------
__global__ void k_stats(const __nv_bfloat16* __restrict__ H,
                        float* __restrict__ colsum, float* __restrict__ colsq) {
    __shared__ float sm[F], sq[F];
    int t = threadIdx.x;            // 256 threads
    if (t < F) { sm[t] = 0.f; sq[t] = 0.f; }
    __syncthreads();
    int pc   = t & 63;
    int rsub = t >> 6;
    int c0 = pc * 2;
    int r0 = blockIdx.x * NS_ROWS;
    float s0 = 0.f, s1 = 0.f, q0 = 0.f, q1 = 0.f;
    for (int r = rsub; r < NS_ROWS; r += 4) {
        int row = r0 + r;
        if (row < NN) {
            float2 f = bf2f2(*(const uint32_t*)&H[(size_t)row * F + c0]);
            s0 += f.x; q0 += f.x * f.x;
            s1 += f.y; q1 += f.y * f.y;
        }
    }
    atomicAdd(&sm[c0], s0);     atomicAdd(&sm[c0 + 1], s1);
    atomicAdd(&sq[c0], q0);     atomicAdd(&sq[c0 + 1], q1);
    __syncthreads();
    if (t < F) {
        atomicAdd(&colsum[t], sm[t]);
        atomicAdd(&colsq[t],  sq[t]);
    }
}

// ---------------- final collapsed layer-2 (nodesum + softmax fused) ----------------
__global__ void k_nsfinal(const __nv_bfloat16* __restrict__ H,
                          const float* __restrict__ colsum, const float* __restrict__ colsq,
                          const float* __restrict__ gam, const float* __restrict__ bet,
                          const float* __restrict__ Ws2, const float* __restrict__ Wn2,
                          const float* __restrict__ b2, float* __restrict__ out) {
    __shared__ float s_sc[F], s_sh[F];
    __shared__ float sm[F], sw[F];
    __shared__ int s_last;
    int t = threadIdx.x;            // 256 threads
    if (t < F) { sm[t] = 0.f; sw[t] = 0.f; }
    bn_coeffs(colsum, colsq, gam, bet, s_sc, s_sh, t);

    int pc   = t & 63;
    int rsub = t >> 6;
    int c0 = pc * 2;
    float2 sc = *(const float2*)&s_sc[c0];
    float2 sh = *(const float2*)&s_sh[c0];
    int r0 = blockIdx.x * NS_ROWS;
    float s0 = 0.f, s1 = 0.f, w0 = 0.f, w1 = 0.f;
    for (int r = rsub; r < NS_ROWS; r += 4) {
        int row = r0 + r;
        if (row < NN) {
            float2 f = bf2f2(*(const uint32_t*)&H[(size_t)row * F + c0]);
            f.x = fmaxf(f.x * sc.x + sh.x, 0.f);
            f.y = fmaxf(f.y * sc.y + sh.y, 0.f);
            float cw = g_gs.cw[row];
            s0 += f.x; s1 += f.y;
            w0 += cw * f.x; w1 += cw * f.y;
        }
    }
    atomicAdd(&sm[c0], s0);     atomicAdd(&sm[c0 + 1], s1);
    atomicAdd(&sw[c0], w0);     atomicAdd(&sw[c0 + 1], w1);
    __syncthreads();
    if (t < F) {
        atomicAdd(&g_acc.msum[t], sm[t]);
        atomicAdd(&g_acc.wa[t],   sw[t]);
    }
    __threadfence();
    if (t == 0) s_last = (atomicAdd(&g_acc.ticket, 1) == gridDim.x - 1) ? 1 : 0;
    __syncthreads();
    if (s_last && t < 32) {
        __threadfence();
        int j = t;
        float inv_n = 1.0f / (float)NN;
        float acc = b2[j];
        for (int k = 0; k < 128; k++) {
            float ms = __ldcg(&g_acc.msum[k]);
            float wv = __ldcg(&g_acc.wa[k]);
            acc += (ms * inv_n) * Ws2[k * 32 + j]
                 + (wv * inv_n) * Wn2[k * 32 + j];
        }
        float m = acc;
        #pragma unroll
        for (int off = 16; off > 0; off >>= 1)
            m = fmaxf(m, __shfl_xor_sync(0xffffffffu, m, off));
        float e = expf(acc - m);
        float s = e;
        #pragma unroll
        for (int off = 16; off > 0; off >>= 1)
            s += __shfl_xor_sync(0xffffffffu, s, off);
        out[j] = e / s;
    }
}

// ---------------- host ----------------

extern "C" void kernel_launch(void* const* d_in, const int* in_sizes, int n_in,
                              void* d_out, int out_size) {
    const float* features = (const float*)d_in[0];
    const int*   src      = (const int*)  d_in[1];
    const int*   dst      = (const int*)  d_in[2];
    const float* Ws0 = (const float*)d_in[3];
    const float* Wn0 = (const float*)d_in[4];
    const float* b0  = (const float*)d_in[5];
    const float* Ws1 = (const float*)d_in[6];
    const float* Wn1 = (const float*)d_in[7];
    const float* b1  = (const float*)d_in[8];
    const float* Ws2 = (const float*)d_in[9];
    const float* Wn2 = (const float*)d_in[10];
    const float* b2  = (const float*)d_in[11];
    const float* g0  = (const float*)d_in[12];
    const float* be0 = (const float*)d_in[13];
    const float* g1  = (const float*)d_in[14];
    const float* be1 = (const float*)d_in[15];
    float* out = (float*)d_out;

    __nv_bfloat16* X0  = nullptr; cudaGetSymbolAddress((void**)&X0,  g_X0);
    __nv_bfloat16* CAT = nullptr; cudaGetSymbolAddress((void**)&CAT, g_CAT);
    __nv_bfloat16* H1  = nullptr; cudaGetSymbolAddress((void**)&H1,  g_H1);
    __nv_bfloat16* H2  = nullptr; cudaGetSymbolAddress((void**)&H2,  g_H2);
    __nv_bfloat16* WT  = nullptr; cudaGetSymbolAddress((void**)&WT,  g_WT);
    void* gs = nullptr;  cudaGetSymbolAddress(&gs,  g_gs);
    void* acc = nullptr; cudaGetSymbolAddress(&acc, g_acc);
    AccumScratch* accp = (AccumScratch*)acc;
    __nv_bfloat16* WT0 = WT;
    __nv_bfloat16* WT1 = WT + 128 * 256;

    // --- zero scratch (memset nodes; don't shift capture index) ---
    cudaMemsetAsync(gs,  0, sizeof(GraphScratch), 0);
    cudaMemsetAsync(acc, 0, sizeof(AccumScratch), 0);

    dim3 ggrid(NBLK_GEMM, 2);

    // kernel launch index (ncu captures index 3 -> k_gemm for layer 0)
    /* 0 */ k_prep<<<NN * 32 / 256, 256>>>(features, dst, Ws0, Wn0, Ws1, Wn1);
    /* 1 */ k_scanfill<<<NBLK_SCAN, SCAN_B>>>(src, dst);

    // --- layer 0 ---
    /* 2 */ k_agg<false><<<NN / 8, 256>>>(X0, nullptr, nullptr, nullptr, nullptr);
    /* 3 */ k_gemm<<<ggrid, 256>>>(CAT, WT0, b0, H1);
    /* 4 */ k_stats<<<NS_BLOCKS, 256>>>(H1, accp->colsumA, accp->colsqA);

    // --- layer 1 (BN0 fused into agg loads) ---
    /* 5 */ k_agg<true><<<NN / 8, 256>>>(H1, accp->colsumA, accp->colsqA, g0, be0);
    /* 6 */ k_gemm<<<ggrid, 256>>>(CAT, WT1, b1, H2);
    /* 7 */ k_stats<<<NS_BLOCKS, 256>>>(H2, accp->colsumB, accp->colsqB);

    // --- layer 2 (collapsed; BN1 fused; softmax in last block) ---
    /* 8 */ k_nsfinal<<<NS_BLOCKS, 256>>>(H2, accp->colsumB, accp->colsqB, g1, be1,
                                          Ws2, Wn2, b2, out);
}

// round 15
// speedup vs baseline: 1.0751x; 1.0751x over previous
#include <cuda_runtime.h>
#include <cuda_bf16.h>
#include <math.h>
#include <stdint.h>

#define NN 100000
#define NE 1600000
#define F  128
#define SCAN_B 1024
#define NBLK_SCAN 98   // ceil(100000/1024)
#define NS_ROWS 400
#define NS_BLOCKS ((NN + NS_ROWS - 1) / NS_ROWS)
#define NBLK_GEMM ((NN + 127) / 128)   // 782
#define NPAD (NBLK_GEMM * 128)          // 100096 padded rows

// ---------------- device scratch (no allocations allowed) ----------------
struct GraphScratch {          // zeroed by memset
    int   deg[NN];
    float cw[NN];
};
struct AccumScratch {          // zeroed by memset
    float colsumA[F], colsqA[F];   // layer-0 stats
    float colsumB[F], colsqB[F];   // layer-1 stats
    float msum[F], wa[F];
    int   ticket;                  // nsfinal last-block ticket
    int   sync2;                   // scanfill grid-sync counter
    int   flag[NBLK_SCAN];
    int   bsum[NBLK_SCAN];
};
static __device__ GraphScratch g_gs;
static __device__ AccumScratch g_acc;

static __device__ int   g_rowstart[NN];
static __device__ int   g_cursor[NN];
static __device__ int   g_col[NE];
static __device__ float g_invdeg[NN];

static __device__ __align__(256) __nv_bfloat16 g_X0[NN * F];      // features bf16
static __device__ __align__(256) __nv_bfloat16 g_CAT[NPAD * 256]; // [Xbn | AGG] (pad rows stay 0)
static __device__ __align__(256) __nv_bfloat16 g_H1[NPAD * F];    // layer outs (pre-BN)
static __device__ __align__(256) __nv_bfloat16 g_H2[NPAD * F];
static __device__ __align__(256) __nv_bfloat16 g_WT[2][128][256]; // W n-major bf16

// ---------------- helpers ----------------

__device__ __forceinline__ void mma_bf16(float c[4], const uint32_t a[4], const uint32_t b[2]) {
    asm volatile(
        "mma.sync.aligned.m16n8k16.row.col.f32.bf16.bf16.f32 "
        "{%0,%1,%2,%3}, {%4,%5,%6,%7}, {%8,%9}, {%0,%1,%2,%3};"
        : "+f"(c[0]), "+f"(c[1]), "+f"(c[2]), "+f"(c[3])
        : "r"(a[0]), "r"(a[1]), "r"(a[2]), "r"(a[3]), "r"(b[0]), "r"(b[1]));
}

__device__ __forceinline__ void ldsm4(uint32_t r[4], uint32_t addr) {
    asm volatile("ldmatrix.sync.aligned.m8n8.x4.shared.b16 {%0,%1,%2,%3}, [%4];"
                 : "=r"(r[0]), "=r"(r[1]), "=r"(r[2]), "=r"(r[3]) : "r"(addr));
}

__device__ __forceinline__ float2 bf2f2(uint32_t p) {
    return __bfloat1622float2(*(const __nv_bfloat162*)&p);
}
__device__ __forceinline__ uint32_t f22bf(float2 f) {
    __nv_bfloat162 h = __float22bfloat162_rn(f);
    return *(const uint32_t*)&h;
}
__device__ __forceinline__ uint32_t smem_u32(const void* p) {
    uint32_t a;
    asm("{ .reg .u64 t; cvta.to.shared.u64 t, %1; cvt.u32.u64 %0, t; }" : "=r"(a) : "l"(p));
    return a;
}
__device__ __forceinline__ void cp_async16(uint32_t dst, const void* src) {
    asm volatile("cp.async.cg.shared.global [%0], [%1], 16;" :: "r"(dst), "l"(src));
}

// Recompute BN affine coefficients into smem (first 128 threads), then sync.
__device__ __forceinline__ void bn_coeffs(const float* __restrict__ colsum,
                                          const float* __restrict__ colsq,
                                          const float* __restrict__ gam,
                                          const float* __restrict__ bet,
                                          float* s_sc, float* s_sh, int tid) {
    if (tid < F) {
        float inv_n = 1.0f / (float)NN;
        float mu  = colsum[tid] * inv_n;
        float var = colsq[tid] * inv_n - mu * mu;
        float sc  = gam[tid] * rsqrtf(var + 1e-5f);
        s_sc[tid] = sc;
        s_sh[tid] = bet[tid] - mu * sc;
    }
    __syncthreads();
}

// ---------------- prep: histogram + feature bf16 + CAT self half + weight transpose ----------------
__global__ void k_prep(const float* __restrict__ feat, const int* __restrict__ dst,
                       const float* __restrict__ Ws0, const float* __restrict__ Wn0,
                       const float* __restrict__ Ws1, const float* __restrict__ Wn1) {
    int gid = blockIdx.x * blockDim.x + threadIdx.x;
    float4 v = ((const float4*)feat)[gid];
    uint2 o;
    o.x = f22bf(make_float2(v.x, v.y));
    o.y = f22bf(make_float2(v.z, v.w));
    *(uint2*)&g_X0[(size_t)gid * 4] = o;
    // layer-0 CAT self half (cols 0..127)
    {
        int node = gid >> 5;
        int c4   = (gid & 31) * 4;
        *(uint2*)&g_CAT[(size_t)node * 256 + c4] = o;
    }
    if (gid < NE / 4) {
        int4 d4 = ((const int4*)dst)[gid];
        atomicAdd(&g_gs.deg[d4.x], 1);
        atomicAdd(&g_gs.deg[d4.y], 1);
        atomicAdd(&g_gs.deg[d4.z], 1);
        atomicAdd(&g_gs.deg[d4.w], 1);
    }
    if (gid < 2 * 256 * 128) {
        int L = gid >> 15;
        int r = gid & 32767;
        int k = r >> 7, n = r & 127;
        const float* W = (L == 0) ? ((k < 128) ? Ws0 : Wn0)
                                  : ((k < 128) ? Ws1 : Wn1);
        g_WT[L][n][k] = __float2bfloat16(W[(k & 127) * 128 + n]);
    }
}

// ---------------- scan + bucket fill (merged; 98 co-resident blocks) ----------------
__global__ void k_scanfill(const int* __restrict__ src, const int* __restrict__ dst) {
    __shared__ int s[SCAN_B];
    __shared__ int s_prefix;
    int t = threadIdx.x;
    int b = blockIdx.x;
    int i = b * SCAN_B + t;
    int v = (i < NN) ? g_gs.deg[i] : 0;
    s[t] = v;
    __syncthreads();
    for (int off = 1; off < SCAN_B; off <<= 1) {
        int x = (t >= off) ? s[t - off] : 0;
        __syncthreads();
        s[t] += x;
        __syncthreads();
    }
    int incl = s[t];
    if (t == SCAN_B - 1) {
        g_acc.bsum[b] = incl;
        __threadfence();
        ((volatile int*)g_acc.flag)[b] = 1;
    }
    if (t < 32) {
        int sum = 0;
        for (int bb = t; bb < b; bb += 32) {
            while (((volatile int*)g_acc.flag)[bb] == 0) {}
            __threadfence();
            sum += ((volatile int*)g_acc.bsum)[bb];
        }
        #pragma unroll
        for (int off = 16; off > 0; off >>= 1)
            sum += __shfl_xor_sync(0xffffffffu, sum, off);
        if (t == 0) s_prefix = sum;
    }
    __syncthreads();
    if (i < NN) {
        int d = v;
        int start = s_prefix + incl - d;
        g_rowstart[i] = start;
        g_cursor[i]   = start;
        g_invdeg[i]   = 1.0f / (float)max(d, 1);
    }
    __threadfence();
    __syncthreads();
    if (t == 0) {
        atomicAdd(&g_acc.sync2, 1);
        while (((volatile int*)&g_acc.sync2)[0] < NBLK_SCAN) {}
    }
    __syncthreads();
    __threadfence();
    int gid = b * SCAN_B + t;
    const int4* s4p = (const int4*)src;
    const int4* d4p = (const int4*)dst;
    for (int q = gid; q < NE / 4; q += NBLK_SCAN * SCAN_B) {
        int4 s4 = s4p[q];
        int4 d4 = d4p[q];
        #define ONEEDGE(ss, dd) {                      \
            int pos = atomicAdd(&g_cursor[dd], 1);      \
            g_col[pos] = ss;                            \
            atomicAdd(&g_gs.cw[ss], g_invdeg[dd]); }
        ONEEDGE(s4.x, d4.x);
        ONEEDGE(s4.y, d4.y);
        ONEEDGE(s4.z, d4.z);
        ONEEDGE(s4.w, d4.w);
        #undef ONEEDGE
    }
}

// ---------------- aggregation: warp-per-node; writes CAT = [own | agg] ----------------
// BN=false: self half already written by k_prep; only the agg half is written.
template<bool BN>
__global__ void k_agg(const __nv_bfloat16* __restrict__ Hin,
                      const float* __restrict__ colsum, const float* __restrict__ colsq,
                      const float* __restrict__ gam, const float* __restrict__ bet) {
    __shared__ float s_sc[F], s_sh[F];
    int tid = threadIdx.x;
    if (BN) bn_coeffs(colsum, colsq, gam, bet, s_sc, s_sh, tid);

    int warp = (blockIdx.x * blockDim.x + tid) >> 5;
    int lane = tid & 31;
    if (warp >= NN) return;
    int c0 = lane * 4;
    float4 sc, sh;
    if (BN) {
        sc = *(const float4*)&s_sc[c0];
        sh = *(const float4*)&s_sh[c0];
    }
    int start = g_rowstart[warp];
    int d     = g_gs.deg[warp];
    float4 acc = make_float4(0.f, 0.f, 0.f, 0.f);

    #define LOADROW(sidx, r01, r23) {                                   \
        uint2 raw = *(const uint2*)(Hin + (size_t)(sidx) * F + c0);     \
        r01 = bf2f2(raw.x); r23 = bf2f2(raw.y);                         \
        if (BN) {                                                        \
            r01.x = fmaxf(r01.x * sc.x + sh.x, 0.f);                     \
            r01.y = fmaxf(r01.y * sc.y + sh.y, 0.f);                     \
            r23.x = fmaxf(r23.x * sc.z + sh.z, 0.f);                     \
            r23.y = fmaxf(r23.y * sc.w + sh.w, 0.f);                     \
        } }

    int j = 0;
    for (; j + 4 <= d; j += 4) {
        int s0 = g_col[start + j];
        int s1 = g_col[start + j + 1];
        int s2 = g_col[start + j + 2];
        int s3 = g_col[start + j + 3];
        float2 a01, a23, b01, b23, c01, c23, d01, d23;
        LOADROW(s0, a01, a23);
        LOADROW(s1, b01, b23);
        LOADROW(s2, c01, c23);
        LOADROW(s3, d01, d23);
        acc.x += (a01.x + b01.x) + (c01.x + d01.x);
        acc.y += (a01.y + b01.y) + (c01.y + d01.y);
        acc.z += (a23.x + b23.x) + (c23.x + d23.x);
        acc.w += (a23.y + b23.y) + (c23.y + d23.y);
    }
    for (; j < d; j++) {
        int s = g_col[start + j];
        float2 a01, a23;
        LOADROW(s, a01, a23);
        acc.x += a01.x; acc.y += a01.y; acc.z += a23.x; acc.w += a23.y;
    }

    if (BN) {
        // own row (BN-applied) -> CAT[:,0:128]
        float2 o01, o23;
        LOADROW(warp, o01, o23);
        uint2 ow;
        ow.x = f22bf(o01);
        ow.y = f22bf(o23);
        *(uint2*)(g_CAT + (size_t)warp * 256 + c0) = ow;
    }
    #undef LOADROW

    float w = g_invdeg[warp];
    uint2 o;
    o.x = f22bf(make_float2(acc.x * w, acc.y * w));
    o.y = f22bf(make_float2(acc.z * w, acc.w * w));
    *(uint2*)(g_CAT + (size_t)warp * 256 + 128 + c0) = o;
}

// ---------------- bf16 tensor-core GEMM, cp.async 2-stage x 64-k, ldmatrix fragments ----------------
// Hout[NPAD][128] = relu(CAT[NPAD][256] @ WT^T + b). No BN, no stats, no bounds.

#define LDH 72                              // bf16 per row (64 data + 8 pad)
#define STAGE_BYTES (128 * LDH * 2)         // 18432

__global__ __launch_bounds__(256) void k_gemm(
    const __nv_bfloat16* __restrict__ CAT,
    const __nv_bfloat16* __restrict__ WT,
    const float* __restrict__ bias,
    __nv_bfloat16* __restrict__ Hout)
{
    __shared__ __align__(16) __nv_bfloat16 As[2][128 * LDH];
    __shared__ __align__(16) __nv_bfloat16 Bs[2][128 * LDH];

    int tid  = threadIdx.x;
    int lane = tid & 31;
    int wid  = tid >> 5;
    int warp_m = wid >> 1;         // 0..3
    int warp_n = wid & 1;          // 0..1
    int g  = lane >> 2;            // 0..7
    int tg = lane & 3;             // 0..3
    int row0 = blockIdx.x * 128;

    uint32_t sA = smem_u32(As);
    uint32_t sB = smem_u32(Bs);

    // ldmatrix per-lane base addresses:
    //   A: row = warp_m*32 + (lane&15) (+ mt*16), k-byte = (lane>>4)*16 (+ ks*32)
    //   B: n   = warp_n*64 + (lane&15) (+ p*16),  k-byte = (lane>>4)*16 (+ ks*32)
    int lm = lane & 15, lh = lane >> 4;
    uint32_t aLm = sA + ((warp_m * 32 + lm) * LDH) * 2 + lh * 16;
    uint32_t bLm = sB + ((warp_n * 64 + lm) * LDH) * 2 + lh * 16;

    #define LOAD_STAGE(kc64, buf) {                                                 \
        _Pragma("unroll")                                                            \
        for (int p = 0; p < 4; p++) {                                                \
            int id = p * 256 + tid;          /* 1024 chunk slots per matrix */       \
            int r = id >> 3, q = id & 7;                                             \
            cp_async16(sA + (buf) * STAGE_BYTES + (r * LDH + q * 8) * 2,             \
                       CAT + (size_t)(row0 + r) * 256 + (kc64) * 64 + q * 8);        \
            cp_async16(sB + (buf) * STAGE_BYTES + (r * LDH + q * 8) * 2,             \
                       WT + (size_t)r * 256 + (kc64) * 64 + q * 8);                  \
        }                                                                            \
        asm volatile("cp.async.commit_group;" ::: "memory"); }

    float c[2][8][4];
    #pragma unroll
    for (int mt = 0; mt < 2; mt++)
        #pragma unroll
        for (int nt = 0; nt < 8; nt++)
            #pragma unroll
            for (int r = 0; r < 4; r++) c[mt][nt][r] = 0.f;

    LOAD_STAGE(0, 0);
    LOAD_STAGE(1, 1);

    for (int i = 0; i < 4; i++) {
        int buf = i & 1;
        if (i < 3) asm volatile("cp.async.wait_group 1;" ::: "memory");
        else       asm volatile("cp.async.wait_group 0;" ::: "memory");
        __syncthreads();

        uint32_t aStage = aLm + buf * STAGE_BYTES;
        uint32_t bStage = bLm + buf * STAGE_BYTES;
        #pragma unroll
        for (int ks = 0; ks < 4; ks++) {
            // A fragments: 2 x ldmatrix.x4 (mt = 0,1)
            uint32_t a[2][4];
            #pragma unroll
            for (int mt = 0; mt < 2; mt++)
                ldsm4(a[mt], aStage + mt * (16 * LDH * 2) + ks * 32);
            // B fragments: 4 x ldmatrix.x4, each covering nt pair (2p, 2p+1)
            // bq[p] = { b[2p][0], b[2p+1][0], b[2p][1], b[2p+1][1] }
            uint32_t bq[4][4];
            #pragma unroll
            for (int p = 0; p < 4; p++)
                ldsm4(bq[p], bStage + p * (16 * LDH * 2) + ks * 32);
            #pragma unroll
            for (int mt = 0; mt < 2; mt++)
                #pragma unroll
                for (int nt = 0; nt < 8; nt++) {
                    uint32_t b2r[2] = { bq[nt >> 1][nt & 1], bq[nt >> 1][(nt & 1) + 2] };
                    mma_bf16(c[mt][nt], a[mt], b2r);
                }
        }
        __syncthreads();
        if (i < 2) LOAD_STAGE(i + 2, buf);
    }
    #undef LOAD_STAGE

    // ---- epilogue: bias + relu + bf16 store (no stats, no bounds) ----
    #pragma unroll
    for (int mt = 0; mt < 2; mt++) {
        int rA = row0 + warp_m * 32 + mt * 16 + g;
        int rB = rA + 8;
        #pragma unroll
        for (int nt = 0; nt < 8; nt++) {
            int col = warp_n * 64 + nt * 8 + tg * 2;
            float2 bb = *(const float2*)&bias[col];
            float v0 = fmaxf(c[mt][nt][0] + bb.x, 0.f);
            float v1 = fmaxf(c[mt][nt][1] + bb.y, 0.f);
            float v2 = fmaxf(c[mt][nt][2] + bb.x, 0.f);
            float v3 = fmaxf(c[mt][nt][3] + bb.y, 0.f);
            *(uint32_t*)&Hout[(size_t)rA * F + col] = f22bf(make_float2(v0, v1));
            *(uint32_t*)&Hout[(size_t)rB * F + col] = f22bf(make_float2(v2, v3));
        }
    }
}

// ---------------- column stats: colsum/colsq over valid rows of H ----------------
__global__ void k_stats(const __nv_bfloat16* __restrict__ H,
                        float* __restrict__ colsum, float* __restrict__ colsq) {
    __shared__ float sm[F], sq[F];
    int t = threadIdx.x;            // 256 threads
    if (t < F) { sm[t] = 0.f; sq[t] = 0.f; }
    __syncthreads();
    int pc   = t & 63;
    int rsub = t >> 6;
    int c0 = pc * 2;
    int r0 = blockIdx.x * NS_ROWS;
    float s0 = 0.f, s1 = 0.f, q0 = 0.f, q1 = 0.f;
    for (int r = rsub; r < NS_ROWS; r += 4) {
        int row = r0 + r;
        if (row < NN) {
            float2 f = bf2f2(*(const uint32_t*)&H[(size_t)row * F + c0]);
            s0 += f.x; q0 += f.x * f.x;
            s1 += f.y; q1 += f.y * f.y;
        }
    }
    atomicAdd(&sm[c0], s0);     atomicAdd(&sm[c0 + 1], s1);
    atomicAdd(&sq[c0], q0);     atomicAdd(&sq[c0 + 1], q1);
    __syncthreads();
    if (t < F) {
        atomicAdd(&colsum[t], sm[t]);
        atomicAdd(&colsq[t],  sq[t]);
    }
}

// ---------------- final collapsed layer-2 (nodesum + softmax fused) ----------------
__global__ void k_nsfinal(const __nv_bfloat16* __restrict__ H,
                          const float* __restrict__ colsum, const float* __restrict__ colsq,
                          const float* __restrict__ gam, const float* __restrict__ bet,
                          const float* __restrict__ Ws2, const float* __restrict__ Wn2,
                          const float* __restrict__ b2, float* __restrict__ out) {
    __shared__ float s_sc[F], s_sh[F];
    __shared__ float sm[F], sw[F];
    __shared__ int s_last;
    int t = threadIdx.x;            // 256 threads
    if (t < F) { sm[t] = 0.f; sw[t] = 0.f; }
    bn_coeffs(colsum, colsq, gam, bet, s_sc, s_sh, t);

    int pc   = t & 63;
    int rsub = t >> 6;
    int c0 = pc * 2;
    float2 sc = *(const float2*)&s_sc[c0];
    float2 sh = *(const float2*)&s_sh[c0];
    int r0 = blockIdx.x * NS_ROWS;
    float s0 = 0.f, s1 = 0.f, w0 = 0.f, w1 = 0.f;
    for (int r = rsub; r < NS_ROWS; r += 4) {
        int row = r0 + r;
        if (row < NN) {
            float2 f = bf2f2(*(const uint32_t*)&H[(size_t)row * F + c0]);
            f.x = fmaxf(f.x * sc.x + sh.x, 0.f);
            f.y = fmaxf(f.y * sc.y + sh.y, 0.f);
            float cw = g_gs.cw[row];
            s0 += f.x; s1 += f.y;
            w0 += cw * f.x; w1 += cw * f.y;
        }
    }
    atomicAdd(&sm[c0], s0);     atomicAdd(&sm[c0 + 1], s1);
    atomicAdd(&sw[c0], w0);     atomicAdd(&sw[c0 + 1], w1);
    __syncthreads();
    if (t < F) {
        atomicAdd(&g_acc.msum[t], sm[t]);
        atomicAdd(&g_acc.wa[t],   sw[t]);
    }
    __threadfence();
    if (t == 0) s_last = (atomicAdd(&g_acc.ticket, 1) == gridDim.x - 1) ? 1 : 0;
    __syncthreads();
    if (s_last && t < 32) {
        __threadfence();
        int j = t;
        float inv_n = 1.0f / (float)NN;
        float acc = b2[j];
        for (int k = 0; k < 128; k++) {
            float ms = __ldcg(&g_acc.msum[k]);
            float wv = __ldcg(&g_acc.wa[k]);
            acc += (ms * inv_n) * Ws2[k * 32 + j]
                 + (wv * inv_n) * Wn2[k * 32 + j];
        }
        float m = acc;
        #pragma unroll
        for (int off = 16; off > 0; off >>= 1)
            m = fmaxf(m, __shfl_xor_sync(0xffffffffu, m, off));
        float e = expf(acc - m);
        float s = e;
        #pragma unroll
        for (int off = 16; off > 0; off >>= 1)
            s += __shfl_xor_sync(0xffffffffu, s, off);
        out[j] = e / s;
    }
}

// ---------------- host ----------------

extern "C" void kernel_launch(void* const* d_in, const int* in_sizes, int n_in,
                              void* d_out, int out_size) {
    const float* features = (const float*)d_in[0];
    const int*   src      = (const int*)  d_in[1];
    const int*   dst      = (const int*)  d_in[2];
    const float* Ws0 = (const float*)d_in[3];
    const float* Wn0 = (const float*)d_in[4];
    const float* b0  = (const float*)d_in[5];
    const float* Ws1 = (const float*)d_in[6];
    const float* Wn1 = (const float*)d_in[7];
    const float* b1  = (const float*)d_in[8];
    const float* Ws2 = (const float*)d_in[9];
    const float* Wn2 = (const float*)d_in[10];
    const float* b2  = (const float*)d_in[11];
    const float* g0  = (const float*)d_in[12];
    const float* be0 = (const float*)d_in[13];
    const float* g1  = (const float*)d_in[14];
    const float* be1 = (const float*)d_in[15];
    float* out = (float*)d_out;

    __nv_bfloat16* X0  = nullptr; cudaGetSymbolAddress((void**)&X0,  g_X0);
    __nv_bfloat16* CAT = nullptr; cudaGetSymbolAddress((void**)&CAT, g_CAT);
    __nv_bfloat16* H1  = nullptr; cudaGetSymbolAddress((void**)&H1,  g_H1);
    __nv_bfloat16* H2  = nullptr; cudaGetSymbolAddress((void**)&H2,  g_H2);
    __nv_bfloat16* WT  = nullptr; cudaGetSymbolAddress((void**)&WT,  g_WT);
    void* gs = nullptr;  cudaGetSymbolAddress(&gs,  g_gs);
    void* acc = nullptr; cudaGetSymbolAddress(&acc, g_acc);
    AccumScratch* accp = (AccumScratch*)acc;
    __nv_bfloat16* WT0 = WT;
    __nv_bfloat16* WT1 = WT + 128 * 256;

    // --- zero scratch (memset nodes; don't shift capture index) ---
    cudaMemsetAsync(gs,  0, sizeof(GraphScratch), 0);
    cudaMemsetAsync(acc, 0, sizeof(AccumScratch), 0);

    // kernel launch index (ncu captures index 3 -> k_gemm for layer 0)
    /* 0 */ k_prep<<<NN * 32 / 256, 256>>>(features, dst, Ws0, Wn0, Ws1, Wn1);
    /* 1 */ k_scanfill<<<NBLK_SCAN, SCAN_B>>>(src, dst);

    // --- layer 0 ---
    /* 2 */ k_agg<false><<<NN / 8, 256>>>(X0, nullptr, nullptr, nullptr, nullptr);
    /* 3 */ k_gemm<<<NBLK_GEMM, 256>>>(CAT, WT0, b0, H1);
    /* 4 */ k_stats<<<NS_BLOCKS, 256>>>(H1, accp->colsumA, accp->colsqA);

    // --- layer 1 (BN0 fused into agg loads) ---
    /* 5 */ k_agg<true><<<NN / 8, 256>>>(H1, accp->colsumA, accp->colsqA, g0, be0);
    /* 6 */ k_gemm<<<NBLK_GEMM, 256>>>(CAT, WT1, b1, H2);
    /* 7 */ k_stats<<<NS_BLOCKS, 256>>>(H2, accp->colsumB, accp->colsqB);

    // --- layer 2 (collapsed; BN1 fused; softmax in last block) ---
    /* 8 */ k_nsfinal<<<NS_BLOCKS, 256>>>(H2, accp->colsumB, accp->colsqB, g1, be1,
                                          Ws2, Wn2, b2, out);
}

// round 16
// speedup vs baseline: 1.1052x; 1.0280x over previous
#include <cuda_runtime.h>
#include <cuda_bf16.h>
#include <math.h>
#include <stdint.h>

#define NN 100000
#define NE 1600000
#define F  128
#define SCAN_B 1024
#define NBLK_SCAN 98   // ceil(100000/1024)
#define NS_ROWS 400
#define NS_BLOCKS ((NN + NS_ROWS - 1) / NS_ROWS)
#define NBLK_GEMM ((NN + 127) / 128)   // 782
#define NPAD (NBLK_GEMM * 128)          // 100096 padded rows

// ---------------- device scratch (no allocations allowed) ----------------
struct GraphScratch {          // zeroed by memset
    int   deg[NN];
    float cw[NN];
};
struct AccumScratch {          // zeroed by memset
    float colsumA[F], colsqA[F];   // layer-0 stats
    float colsumB[F], colsqB[F];   // layer-1 stats
    float msum[F], wa[F];
    int   ticket;                  // nsfinal last-block ticket
    int   sync2;                   // scanfill grid-sync counter
    int   flag[NBLK_SCAN];
    int   bsum[NBLK_SCAN];
};
static __device__ GraphScratch g_gs;
static __device__ AccumScratch g_acc;

static __device__ int   g_rowstart[NN];
static __device__ int   g_cursor[NN];
static __device__ int   g_col[NE];
static __device__ float g_invdeg[NN];

static __device__ __align__(256) __nv_bfloat16 g_X0[NN * F];      // features bf16; reused as H1bn
static __device__ __align__(256) __nv_bfloat16 g_CAT[NPAD * 256]; // [Xbn | AGG] (pad rows stay 0)
static __device__ __align__(256) __nv_bfloat16 g_H1[NPAD * F];    // layer outs (pre-BN)
static __device__ __align__(256) __nv_bfloat16 g_H2[NPAD * F];
static __device__ __align__(256) __nv_bfloat16 g_WT[2][128][256]; // W n-major bf16

// ---------------- helpers ----------------

__device__ __forceinline__ void mma_bf16(float c[4], const uint32_t a[4], const uint32_t b[2]) {
    asm volatile(
        "mma.sync.aligned.m16n8k16.row.col.f32.bf16.bf16.f32 "
        "{%0,%1,%2,%3}, {%4,%5,%6,%7}, {%8,%9}, {%0,%1,%2,%3};"
        : "+f"(c[0]), "+f"(c[1]), "+f"(c[2]), "+f"(c[3])
        : "r"(a[0]), "r"(a[1]), "r"(a[2]), "r"(a[3]), "r"(b[0]), "r"(b[1]));
}

__device__ __forceinline__ void ldsm4(uint32_t r[4], uint32_t addr) {
    asm volatile("ldmatrix.sync.aligned.m8n8.x4.shared.b16 {%0,%1,%2,%3}, [%4];"
                 : "=r"(r[0]), "=r"(r[1]), "=r"(r[2]), "=r"(r[3]) : "r"(addr));
}

__device__ __forceinline__ uint32_t hadd2(uint32_t a, uint32_t b) {
    uint32_t r;
    asm("add.rn.bf16x2 %0, %1, %2;" : "=r"(r) : "r"(a), "r"(b));
    return r;
}

__device__ __forceinline__ float2 bf2f2(uint32_t p) {
    return __bfloat1622float2(*(const __nv_bfloat162*)&p);
}
__device__ __forceinline__ uint32_t f22bf(float2 f) {
    __nv_bfloat162 h = __float22bfloat162_rn(f);
    return *(const uint32_t*)&h;
}
__device__ __forceinline__ uint32_t smem_u32(const void* p) {
    uint32_t a;
    asm("{ .reg .u64 t; cvta.to.shared.u64 t, %1; cvt.u32.u64 %0, t; }" : "=r"(a) : "l"(p));
    return a;
}
__device__ __forceinline__ void cp_async16(uint32_t dst, const void* src) {
    asm volatile("cp.async.cg.shared.global [%0], [%1], 16;" :: "r"(dst), "l"(src));
}

// Recompute BN affine coefficients into smem (first 128 threads), then sync.
__device__ __forceinline__ void bn_coeffs(const float* __restrict__ colsum,
                                          const float* __restrict__ colsq,
                                          const float* __restrict__ gam,
                                          const float* __restrict__ bet,
                                          float* s_sc, float* s_sh, int tid) {
    if (tid < F) {
        float inv_n = 1.0f / (float)NN;
        float mu  = colsum[tid] * inv_n;
        float var = colsq[tid] * inv_n - mu * mu;
        float sc  = gam[tid] * rsqrtf(var + 1e-5f);
        s_sc[tid] = sc;
        s_sh[tid] = bet[tid] - mu * sc;
    }
    __syncthreads();
}

// ---------------- k_wt: weight transpose ----------------
__global__ void k_wt(const float* __restrict__ Ws0, const float* __restrict__ Wn0,
                     const float* __restrict__ Ws1, const float* __restrict__ Wn1) {
    int gid = blockIdx.x * blockDim.x + threadIdx.x;   // 65536 threads
    int L = gid >> 15;
    int r = gid & 32767;
    int k = r >> 7, n = r & 127;
    const float* W = (L == 0) ? ((k < 128) ? Ws0 : Wn0)
                              : ((k < 128) ? Ws1 : Wn1);
    g_WT[L][n][k] = __float2bfloat16(W[(k & 127) * 128 + n]);
}

// ---------------- k_feat: feature bf16 conversion + CAT self half ----------------
__global__ void k_feat(const float* __restrict__ feat) {
    int gid = blockIdx.x * blockDim.x + threadIdx.x;   // NN*32 slots
    float4 v = ((const float4*)feat)[gid];
    uint2 o;
    o.x = f22bf(make_float2(v.x, v.y));
    o.y = f22bf(make_float2(v.z, v.w));
    *(uint2*)&g_X0[(size_t)gid * 4] = o;
    int node = gid >> 5;
    int c4   = (gid & 31) * 4;
    *(uint2*)&g_CAT[(size_t)node * 256 + c4] = o;
}

// ---------------- k_hist: degree histogram ----------------
__global__ void k_hist(const int* __restrict__ dst) {
    int gid = blockIdx.x * blockDim.x + threadIdx.x;
    if (gid < NE / 4) {
        int4 d4 = ((const int4*)dst)[gid];
        atomicAdd(&g_gs.deg[d4.x], 1);
        atomicAdd(&g_gs.deg[d4.y], 1);
        atomicAdd(&g_gs.deg[d4.z], 1);
        atomicAdd(&g_gs.deg[d4.w], 1);
    }
}

// ---------------- scan + bucket fill (merged; 98 co-resident blocks) ----------------
__global__ void k_scanfill(const int* __restrict__ src, const int* __restrict__ dst) {
    __shared__ int s[SCAN_B];
    __shared__ int s_prefix;
    int t = threadIdx.x;
    int b = blockIdx.x;
    int i = b * SCAN_B + t;
    int v = (i < NN) ? g_gs.deg[i] : 0;
    s[t] = v;
    __syncthreads();
    for (int off = 1; off < SCAN_B; off <<= 1) {
        int x = (t >= off) ? s[t - off] : 0;
        __syncthreads();
        s[t] += x;
        __syncthreads();
    }
    int incl = s[t];
    if (t == SCAN_B - 1) {
        g_acc.bsum[b] = incl;
        __threadfence();
        ((volatile int*)g_acc.flag)[b] = 1;
    }
    if (t < 32) {
        int sum = 0;
        for (int bb = t; bb < b; bb += 32) {
            while (((volatile int*)g_acc.flag)[bb] == 0) {}
            __threadfence();
            sum += ((volatile int*)g_acc.bsum)[bb];
        }
        #pragma unroll
        for (int off = 16; off > 0; off >>= 1)
            sum += __shfl_xor_sync(0xffffffffu, sum, off);
        if (t == 0) s_prefix = sum;
    }
    __syncthreads();
    if (i < NN) {
        int d = v;
        int start = s_prefix + incl - d;
        g_rowstart[i] = start;
        g_cursor[i]   = start;
        g_invdeg[i]   = 1.0f / (float)max(d, 1);
    }
    __threadfence();
    __syncthreads();
    if (t == 0) {
        atomicAdd(&g_acc.sync2, 1);
        while (((volatile int*)&g_acc.sync2)[0] < NBLK_SCAN) {}
    }
    __syncthreads();
    __threadfence();
    int gid = b * SCAN_B + t;
    const int4* s4p = (const int4*)src;
    const int4* d4p = (const int4*)dst;
    for (int q = gid; q < NE / 4; q += NBLK_SCAN * SCAN_B) {
        int4 s4 = s4p[q];
        int4 d4 = d4p[q];
        #define ONEEDGE(ss, dd) {                      \
            int pos = atomicAdd(&g_cursor[dd], 1);      \
            g_col[pos] = ss;                            \
            atomicAdd(&g_gs.cw[ss], g_invdeg[dd]); }
        ONEEDGE(s4.x, d4.x);
        ONEEDGE(s4.y, d4.y);
        ONEEDGE(s4.z, d4.z);
        ONEEDGE(s4.w, d4.w);
        #undef ONEEDGE
    }
}

// ---------------- aggregation: warp-per-node, pairwise bf16 tree ----------------
// Writes CAT agg-half only (self-half by k_feat / k_bnapply).
__global__ void k_agg(const __nv_bfloat16* __restrict__ Hin) {
    int tid = threadIdx.x;
    int warp = (blockIdx.x * blockDim.x + tid) >> 5;
    int lane = tid & 31;
    if (warp >= NN) return;
    int c0 = lane * 4;
    int start = g_rowstart[warp];
    int d     = g_gs.deg[warp];
    float4 acc = make_float4(0.f, 0.f, 0.f, 0.f);

    int j = 0;
    for (; j + 4 <= d; j += 4) {
        int s0 = g_col[start + j];
        int s1 = g_col[start + j + 1];
        int s2 = g_col[start + j + 2];
        int s3 = g_col[start + j + 3];
        uint2 rA = *(const uint2*)(Hin + (size_t)s0 * F + c0);
        uint2 rB = *(const uint2*)(Hin + (size_t)s1 * F + c0);
        uint2 rC = *(const uint2*)(Hin + (size_t)s2 * F + c0);
        uint2 rD = *(const uint2*)(Hin + (size_t)s3 * F + c0);
        uint32_t s01 = hadd2(hadd2(rA.x, rB.x), hadd2(rC.x, rD.x));
        uint32_t s23 = hadd2(hadd2(rA.y, rB.y), hadd2(rC.y, rD.y));
        float2 f01 = bf2f2(s01), f23 = bf2f2(s23);
        acc.x += f01.x; acc.y += f01.y; acc.z += f23.x; acc.w += f23.y;
    }
    for (; j < d; j++) {
        int s = g_col[start + j];
        uint2 r = *(const uint2*)(Hin + (size_t)s * F + c0);
        float2 f01 = bf2f2(r.x), f23 = bf2f2(r.y);
        acc.x += f01.x; acc.y += f01.y; acc.z += f23.x; acc.w += f23.y;
    }

    float w = g_invdeg[warp];
    uint2 o;
    o.x = f22bf(make_float2(acc.x * w, acc.y * w));
    o.y = f22bf(make_float2(acc.z * w, acc.w * w));
    *(uint2*)(g_CAT + (size_t)warp * 256 + 128 + c0) = o;
}

// ---------------- k_bnapply: H (pre-BN) -> relu(BN(H)) into Hbn + CAT self half ----------------
__global__ void k_bnapply(const __nv_bfloat16* __restrict__ H,
                          const float* __restrict__ colsum, const float* __restrict__ colsq,
                          const float* __restrict__ gam, const float* __restrict__ bet,
                          __nv_bfloat16* __restrict__ Hbn) {
    __shared__ float s_sc[F], s_sh[F];
    int tid = threadIdx.x;
    bn_coeffs(colsum, colsq, gam, bet, s_sc, s_sh, tid);
    int gid = blockIdx.x * blockDim.x + tid;   // NN*32 uint2 slots
    int node = gid >> 5;
    int c4   = (gid & 31) * 4;
    uint2 raw = *(const uint2*)(H + (size_t)node * F + c4);
    float2 f01 = bf2f2(raw.x);
    float2 f23 = bf2f2(raw.y);
    float4 sc = *(const float4*)&s_sc[c4];
    float4 sh = *(const float4*)&s_sh[c4];
    f01.x = fmaxf(f01.x * sc.x + sh.x, 0.f);
    f01.y = fmaxf(f01.y * sc.y + sh.y, 0.f);
    f23.x = fmaxf(f23.x * sc.z + sh.z, 0.f);
    f23.y = fmaxf(f23.y * sc.w + sh.w, 0.f);
    uint2 o;
    o.x = f22bf(f01);
    o.y = f22bf(f23);
    *(uint2*)(Hbn + (size_t)node * F + c4) = o;
    *(uint2*)(g_CAT + (size_t)node * 256 + c4) = o;
}

// ---------------- bf16 tensor-core GEMM, cp.async 2-stage x 64-k, ldmatrix fragments ----------------
// Hout[NPAD][128] = relu(CAT[NPAD][256] @ WT^T + b). No BN, no stats, no bounds.

#define LDH 72                              // bf16 per row (64 data + 8 pad)
#define STAGE_BYTES (128 * LDH * 2)         // 18432

__global__ __launch_bounds__(256) void k_gemm(
    const __nv_bfloat16* __restrict__ CAT,
    const __nv_bfloat16* __restrict__ WT,
    const float* __restrict__ bias,
    __nv_bfloat16* __restrict__ Hout)
{
    __shared__ __align__(16) __nv_bfloat16 As[2][128 * LDH];
    __shared__ __align__(16) __nv_bfloat16 Bs[2][128 * LDH];

    int tid  = threadIdx.x;
    int lane = tid & 31;
    int wid  = tid >> 5;
    int warp_m = wid >> 1;         // 0..3
    int warp_n = wid & 1;          // 0..1
    int g  = lane >> 2;            // 0..7
    int tg = lane & 3;             // 0..3
    int row0 = blockIdx.x * 128;

    uint32_t sA = smem_u32(As);
    uint32_t sB = smem_u32(Bs);

    int lm = lane & 15, lh = lane >> 4;
    uint32_t aLm = sA + ((warp_m * 32 + lm) * LDH) * 2 + lh * 16;
    uint32_t bLm = sB + ((warp_n * 64 + lm) * LDH) * 2 + lh * 16;

    #define LOAD_STAGE(kc64, buf) {                                                 \
        _Pragma("unroll")                                                            \
        for (int p = 0; p < 4; p++) {                                                \
            int id = p * 256 + tid;                                                  \
            int r = id >> 3, q = id & 7;                                             \
            cp_async16(sA + (buf) * STAGE_BYTES + (r * LDH + q * 8) * 2,             \
                       CAT + (size_t)(row0 + r) * 256 + (kc64) * 64 + q * 8);        \
            cp_async16(sB + (buf) * STAGE_BYTES + (r * LDH + q * 8) * 2,             \
                       WT + (size_t)r * 256 + (kc64) * 64 + q * 8);                  \
        }                                                                            \
        asm volatile("cp.async.commit_group;" ::: "memory"); }

    float c[2][8][4];
    #pragma unroll
    for (int mt = 0; mt < 2; mt++)
        #pragma unroll
        for (int nt = 0; nt < 8; nt++)
            #pragma unroll
            for (int r = 0; r < 4; r++) c[mt][nt][r] = 0.f;

    LOAD_STAGE(0, 0);
    LOAD_STAGE(1, 1);

    for (int i = 0; i < 4; i++) {
        int buf = i & 1;
        if (i < 3) asm volatile("cp.async.wait_group 1;" ::: "memory");
        else       asm volatile("cp.async.wait_group 0;" ::: "memory");
        __syncthreads();

        uint32_t aStage = aLm + buf * STAGE_BYTES;
        uint32_t bStage = bLm + buf * STAGE_BYTES;
        #pragma unroll
        for (int ks = 0; ks < 4; ks++) {
            uint32_t a[2][4];
            #pragma unroll
            for (int mt = 0; mt < 2; mt++)
                ldsm4(a[mt], aStage + mt * (16 * LDH * 2) + ks * 32);
            uint32_t bq[4][4];
            #pragma unroll
            for (int p = 0; p < 4; p++)
                ldsm4(bq[p], bStage + p * (16 * LDH * 2) + ks * 32);
            #pragma unroll
            for (int mt = 0; mt < 2; mt++)
                #pragma unroll
                for (int nt = 0; nt < 8; nt++) {
                    uint32_t b2r[2] = { bq[nt >> 1][nt & 1], bq[nt >> 1][(nt & 1) + 2] };
                    mma_bf16(c[mt][nt], a[mt], b2r);
                }
        }
        __syncthreads();
        if (i < 2) LOAD_STAGE(i + 2, buf);
    }
    #undef LOAD_STAGE

    // ---- epilogue: bias + relu + bf16 store ----
    #pragma unroll
    for (int mt = 0; mt < 2; mt++) {
        int rA = row0 + warp_m * 32 + mt * 16 + g;
        int rB = rA + 8;
        #pragma unroll
        for (int nt = 0; nt < 8; nt++) {
            int col = warp_n * 64 + nt * 8 + tg * 2;
            float2 bb = *(const float2*)&bias[col];
            float v0 = fmaxf(c[mt][nt][0] + bb.x, 0.f);
            float v1 = fmaxf(c[mt][nt][1] + bb.y, 0.f);
            float v2 = fmaxf(c[mt][nt][2] + bb.x, 0.f);
            float v3 = fmaxf(c[mt][nt][3] + bb.y, 0.f);
            *(uint32_t*)&Hout[(size_t)rA * F + col] = f22bf(make_float2(v0, v1));
            *(uint32_t*)&Hout[(size_t)rB * F + col] = f22bf(make_float2(v2, v3));
        }
    }
}

// ---------------- column stats: colsum/colsq over valid rows of H ----------------
__global__ void k_stats(const __nv_bfloat16* __restrict__ H,
                        float* __restrict__ colsum, float* __restrict__ colsq) {
    __shared__ float sm[F], sq[F];
    int t = threadIdx.x;            // 256 threads
    if (t < F) { sm[t] = 0.f; sq[t] = 0.f; }
    __syncthreads();
    int pc   = t & 63;
    int rsub = t >> 6;
    int c0 = pc * 2;
    int r0 = blockIdx.x * NS_ROWS;
    float s0 = 0.f, s1 = 0.f, q0 = 0.f, q1 = 0.f;
    for (int r = rsub; r < NS_ROWS; r += 4) {
        int row = r0 + r;
        if (row < NN) {
            float2 f = bf2f2(*(const uint32_t*)&H[(size_t)row * F + c0]);
            s0 += f.x; q0 += f.x * f.x;
            s1 += f.y; q1 += f.y * f.y;
        }
    }
    atomicAdd(&sm[c0], s0);     atomicAdd(&sm[c0 + 1], s1);
    atomicAdd(&sq[c0], q0);     atomicAdd(&sq[c0 + 1], q1);
    __syncthreads();
    if (t < F) {
        atomicAdd(&colsum[t], sm[t]);
        atomicAdd(&colsq[t],  sq[t]);
    }
}

// ---------------- final collapsed layer-2 (nodesum + softmax fused) ----------------
__global__ void k_nsfinal(const __nv_bfloat16* __restrict__ H,
                          const float* __restrict__ colsum, const float* __restrict__ colsq,
                          const float* __restrict__ gam, const float* __restrict__ bet,
                          const float* __restrict__ Ws2, const float* __restrict__ Wn2,
                          const float* __restrict__ b2, float* __restrict__ out) {
    __shared__ float s_sc[F], s_sh[F];
    __shared__ float sm[F], sw[F];
    __shared__ int s_last;
    int t = threadIdx.x;            // 256 threads
    if (t < F) { sm[t] = 0.f; sw[t] = 0.f; }
    bn_coeffs(colsum, colsq, gam, bet, s_sc, s_sh, t);

    int pc   = t & 63;
    int rsub = t >> 6;
    int c0 = pc * 2;
    float2 sc = *(const float2*)&s_sc[c0];
    float2 sh = *(const float2*)&s_sh[c0];
    int r0 = blockIdx.x * NS_ROWS;
    float s0 = 0.f, s1 = 0.f, w0 = 0.f, w1 = 0.f;
    for (int r = rsub; r < NS_ROWS; r += 4) {
        int row = r0 + r;
        if (row < NN) {
            float2 f = bf2f2(*(const uint32_t*)&H[(size_t)row * F + c0]);
            f.x = fmaxf(f.x * sc.x + sh.x, 0.f);
            f.y = fmaxf(f.y * sc.y + sh.y, 0.f);
            float cw = g_gs.cw[row];
            s0 += f.x; s1 += f.y;
            w0 += cw * f.x; w1 += cw * f.y;
        }
    }
    atomicAdd(&sm[c0], s0);     atomicAdd(&sm[c0 + 1], s1);
    atomicAdd(&sw[c0], w0);     atomicAdd(&sw[c0 + 1], w1);
    __syncthreads();
    if (t < F) {
        atomicAdd(&g_acc.msum[t], sm[t]);
        atomicAdd(&g_acc.wa[t],   sw[t]);
    }
    __threadfence();
    if (t == 0) s_last = (atomicAdd(&g_acc.ticket, 1) == gridDim.x - 1) ? 1 : 0;
    __syncthreads();
    if (s_last && t < 32) {
        __threadfence();
        int j = t;
        float inv_n = 1.0f / (float)NN;
        float acc = b2[j];
        for (int k = 0; k < 128; k++) {
            float ms = __ldcg(&g_acc.msum[k]);
            float wv = __ldcg(&g_acc.wa[k]);
            acc += (ms * inv_n) * Ws2[k * 32 + j]
                 + (wv * inv_n) * Wn2[k * 32 + j];
        }
        float m = acc;
        #pragma unroll
        for (int off = 16; off > 0; off >>= 1)
            m = fmaxf(m, __shfl_xor_sync(0xffffffffu, m, off));
        float e = expf(acc - m);
        float s = e;
        #pragma unroll
        for (int off = 16; off > 0; off >>= 1)
            s += __shfl_xor_sync(0xffffffffu, s, off);
        out[j] = e / s;
    }
}

// ---------------- host ----------------

extern "C" void kernel_launch(void* const* d_in, const int* in_sizes, int n_in,
                              void* d_out, int out_size) {
    const float* features = (const float*)d_in[0];
    const int*   src      = (const int*)  d_in[1];
    const int*   dst      = (const int*)  d_in[2];
    const float* Ws0 = (const float*)d_in[3];
    const float* Wn0 = (const float*)d_in[4];
    const float* b0  = (const float*)d_in[5];
    const float* Ws1 = (const float*)d_in[6];
    const float* Wn1 = (const float*)d_in[7];
    const float* b1  = (const float*)d_in[8];
    const float* Ws2 = (const float*)d_in[9];
    const float* Wn2 = (const float*)d_in[10];
    const float* b2  = (const float*)d_in[11];
    const float* g0  = (const float*)d_in[12];
    const float* be0 = (const float*)d_in[13];
    const float* g1  = (const float*)d_in[14];
    const float* be1 = (const float*)d_in[15];
    float* out = (float*)d_out;

    __nv_bfloat16* X0  = nullptr; cudaGetSymbolAddress((void**)&X0,  g_X0);
    __nv_bfloat16* CAT = nullptr; cudaGetSymbolAddress((void**)&CAT, g_CAT);
    __nv_bfloat16* H1  = nullptr; cudaGetSymbolAddress((void**)&H1,  g_H1);
    __nv_bfloat16* H2  = nullptr; cudaGetSymbolAddress((void**)&H2,  g_H2);
    __nv_bfloat16* WT  = nullptr; cudaGetSymbolAddress((void**)&WT,  g_WT);
    void* gs = nullptr;  cudaGetSymbolAddress(&gs,  g_gs);
    void* acc = nullptr; cudaGetSymbolAddress(&acc, g_acc);
    AccumScratch* accp = (AccumScratch*)acc;
    __nv_bfloat16* WT0 = WT;
    __nv_bfloat16* WT1 = WT + 128 * 256;

    // --- zero scratch (memset nodes; don't shift capture index) ---
    cudaMemsetAsync(gs,  0, sizeof(GraphScratch), 0);
    cudaMemsetAsync(acc, 0, sizeof(AccumScratch), 0);

    // kernel launch index (ncu captures index 3 -> k_scanfill)
    /* 0 */ k_wt<<<256, 256>>>(Ws0, Wn0, Ws1, Wn1);
    /* 1 */ k_feat<<<NN * 32 / 256, 256>>>(features);
    /* 2 */ k_hist<<<(NE / 4 + 255) / 256, 256>>>(dst);
    /* 3 */ k_scanfill<<<NBLK_SCAN, SCAN_B>>>(src, dst);   // <- profiled

    // --- layer 0 ---
    /* 4 */ k_agg<<<NN / 8, 256>>>(X0);
    /* 5 */ k_gemm<<<NBLK_GEMM, 256>>>(CAT, WT0, b0, H1);
    /* 6 */ k_stats<<<NS_BLOCKS, 256>>>(H1, accp->colsumA, accp->colsqA);

    // --- layer 1 (BN0 applied once by k_bnapply; X0 reused as H1bn) ---
    /* 7 */ k_bnapply<<<NN * 32 / 256, 256>>>(H1, accp->colsumA, accp->colsqA, g0, be0, X0);
    /* 8 */ k_agg<<<NN / 8, 256>>>(X0);
    /* 9 */ k_gemm<<<NBLK_GEMM, 256>>>(CAT, WT1, b1, H2);
    /* 10 */ k_stats<<<NS_BLOCKS, 256>>>(H2, accp->colsumB, accp->colsqB);

    // --- layer 2 (collapsed; BN1 fused; softmax in last block) ---
    /* 11 */ k_nsfinal<<<NS_BLOCKS, 256>>>(H2, accp->colsumB, accp->colsqB, g1, be1,
                                           Ws2, Wn2, b2, out);
}